// round 7
// baseline (speedup 1.0000x reference)
#include <cuda_runtime.h>

// PeakSense: out[b,p] = sum_i exp(-0.5*(mass[b,i]-mu[p])^2 * exp(-lv[p])) * iv[b,i],
// terms with arg < -10 dropped. Masses sorted per batch -> per-peak window.
//
// R7 = R6 with the rank-search off-by-one fixed.
//  - Branchless 12-step rank search + FINAL CORRECTION step (the standard
//    lower-bound form: pos += (a[pos] cmp t) at the end; without it rank==4096
//    is unreachable and the last element gets dropped from top windows).
//  - (mass, iv) staged interleaved as float2 in smem: main loop = 1x LDS.64 + 5 FP.
//  - Exact window, unroll x2 with dual accumulators. 1024 CTAs, 8 lanes/peak.

#define PS_B 128
#define PS_L 4096
#define PS_N 256
#define GROUPS 8                          // blocks per batch
#define PEAKS_PER_BLOCK (PS_N / GROUPS)   // 32
#define LANES 8                           // lanes per peak
#define THREADS (PEAKS_PER_BLOCK * LANES) // 256
#define LOG2E 1.4426950408889634f

__global__ __launch_bounds__(THREADS)
void peaksense_kernel(const float* __restrict__ mu,
                      const float* __restrict__ lv,
                      const float* __restrict__ masses,
                      const float* __restrict__ intens,
                      float* __restrict__ out) {
    __shared__ float2 sm_pair[PS_L];      // {mass, iv}, 32 KB

    const int b    = blockIdx.y;
    const int tid  = threadIdx.x;
    const int p    = blockIdx.x * PEAKS_PER_BLOCK + (tid >> 3);
    const int q    = tid & 7;             // lane within peak group
    const int lane = tid & 31;

    // Stage masses+intensities interleaved: float4 loads, float4 stores.
    {
        const float4* m4 = reinterpret_cast<const float4*>(masses + (size_t)b * PS_L);
        const float4* i4 = reinterpret_cast<const float4*>(intens + (size_t)b * PS_L);
        #pragma unroll
        for (int j = tid; j < PS_L / 4; j += THREADS) {
            float4 mm = m4[j];
            float4 yy = i4[j];
            float4* dst = reinterpret_cast<float4*>(&sm_pair[4 * j]);
            dst[0] = make_float4(mm.x, yy.x, mm.y, yy.y);
            dst[1] = make_float4(mm.z, yy.z, mm.w, yy.w);
        }
    }

    const float m      = mu[p];
    const float inv_s2 = __expf(-lv[p]);  // 1/sigma^2
    // arg >= -10  <=>  d^2 <= 20/inv_s2. Inflate R slightly so [lo,hi) is a
    // superset of the passing set; the exact in-loop select is the filter.
    const float R   = sqrtf(20.0f / inv_s2) * 1.0002f + 1e-5f;
    const float lob = m - R;
    const float hib = m + R;

    __syncthreads();

    // Branchless rank search. Lanes 0-3: rank of lob with '<'  (= first >= lob).
    // Lanes 4-7: rank of hib with '<=' (= first > hib). 12 unrolled steps plus
    // the final correction (pos can otherwise never reach 4096).
    const bool  isLo   = (q < 4);
    const float target = isLo ? lob : hib;
    int pos = 0;
    #pragma unroll
    for (int s = PS_L / 2; s > 0; s >>= 1) {
        float v = sm_pair[pos + s - 1].x;
        bool adv = isLo ? (v < target) : (v <= target);
        pos += adv ? s : 0;
    }
    {   // final correction: pos in [0, 4095]; rank may be pos or pos+1.
        float v = sm_pair[pos].x;
        bool adv = isLo ? (v < target) : (v <= target);
        pos += adv ? 1 : 0;
    }
    const int base = lane & ~7;           // first lane of this peak group
    const int lo = __shfl_sync(0xFFFFFFFF, pos, base + 0);
    const int hi = __shfl_sync(0xFFFFFFFF, pos, base + 4);

    // w = exp2(c2*d*d), keep iff c2*d*d >= -10*log2(e).
    const float c2  = -0.5f * inv_s2 * LOG2E;
    const float th2 = -10.0f * LOG2E;

    float acc0 = 0.0f, acc1 = 0.0f;
    int i = lo + q;
    #pragma unroll 1
    for (; i + LANES < hi; i += 2 * LANES) {
        float2 e0 = sm_pair[i];
        float2 e1 = sm_pair[i + LANES];
        float d0 = e0.x - m;
        float d1 = e1.x - m;
        float a0 = c2 * d0 * d0;
        float a1 = c2 * d1 * d1;
        float w0 = (a0 >= th2) ? exp2f(a0) : 0.0f;
        float w1 = (a1 >= th2) ? exp2f(a1) : 0.0f;
        acc0 = fmaf(w0, e0.y, acc0);
        acc1 = fmaf(w1, e1.y, acc1);
    }
    if (i < hi) {
        float2 e = sm_pair[i];
        float d = e.x - m;
        float a = c2 * d * d;
        float w = (a >= th2) ? exp2f(a) : 0.0f;
        acc0 = fmaf(w, e.y, acc0);
    }

    // Reduce the 8 lanes of this peak.
    float acc = acc0 + acc1;
    acc += __shfl_xor_sync(0xFFFFFFFF, acc, 1);
    acc += __shfl_xor_sync(0xFFFFFFFF, acc, 2);
    acc += __shfl_xor_sync(0xFFFFFFFF, acc, 4);

    if (q == 0) out[(size_t)b * PS_N + p] = acc;
}

extern "C" void kernel_launch(void* const* d_in, const int* in_sizes, int n_in,
                              void* d_out, int out_size) {
    const float* mu     = (const float*)d_in[0];
    const float* lv     = (const float*)d_in[1];
    const float* masses = (const float*)d_in[2];
    const float* intens = (const float*)d_in[3];
    float* out = (float*)d_out;

    dim3 grid(GROUPS, PS_B);
    peaksense_kernel<<<grid, THREADS>>>(mu, lv, masses, intens, out);
}

// round 8
// speedup vs baseline: 1.0625x; 1.0625x over previous
#include <cuda_runtime.h>

// PeakSense: out[b,p] = sum_i exp(-0.5*(mass[b,i]-mu[p])^2 * exp(-lv[p])) * iv[b,i],
// terms with arg < -10 dropped. Masses sorted per batch -> per-peak window.
//
// R8 = R5 skeleton (mass-only smem, iv from global, 1024 CTAs, 8 lanes/peak)
//    + R7's verified branchless rank search (12 steps + final correction)
//    + inline ex2.approx.f32 (libm exp2f without fast-math is ~20 instr; the
//      hidden hot-loop bloat was ~180 instr/thread = the round 3-7 plateau).

#define PS_B 128
#define PS_L 4096
#define PS_N 256
#define GROUPS 8                          // blocks per batch
#define PEAKS_PER_BLOCK (PS_N / GROUPS)   // 32
#define LANES 8                           // lanes per peak
#define THREADS (PEAKS_PER_BLOCK * LANES) // 256
#define LOG2E 1.4426950408889634f

__device__ __forceinline__ float ex2_approx(float x) {
    float r;
    asm("ex2.approx.f32 %0, %1;" : "=f"(r) : "f"(x));
    return r;
}

__global__ __launch_bounds__(THREADS)
void peaksense_kernel(const float* __restrict__ mu,
                      const float* __restrict__ lv,
                      const float* __restrict__ masses,
                      const float* __restrict__ intens,
                      float* __restrict__ out) {
    __shared__ float sm_mass[PS_L];       // 16 KB

    const int b    = blockIdx.y;
    const int tid  = threadIdx.x;
    const int p    = blockIdx.x * PEAKS_PER_BLOCK + (tid >> 3);
    const int q    = tid & 7;             // lane within peak group
    const int lane = tid & 31;

    // Stage this batch's masses into shared (float4, 4 per thread, MLP=4).
    {
        const float4* m4 = reinterpret_cast<const float4*>(masses + (size_t)b * PS_L);
        float4* s4 = reinterpret_cast<float4*>(sm_mass);
        #pragma unroll
        for (int i = tid; i < PS_L / 4; i += THREADS) s4[i] = m4[i];
    }

    const float* __restrict__ iv = intens + (size_t)b * PS_L;

    const float m      = mu[p];
    const float inv_s2 = __expf(-lv[p]);  // 1/sigma^2
    // arg >= -10  <=>  d^2 <= 20/inv_s2. Inflate R slightly so [lo,hi) is a
    // superset of the passing set; the exact in-loop select is the filter.
    const float R   = sqrtf(20.0f / inv_s2) * 1.0002f + 1e-5f;
    const float lob = m - R;
    const float hib = m + R;

    __syncthreads();

    // Branchless rank search (verified in R7). Lanes 0-3: first >= lob.
    // Lanes 4-7: first > hib. 12 unrolled steps + final correction.
    const bool  isLo   = (q < 4);
    const float target = isLo ? lob : hib;
    int pos = 0;
    #pragma unroll
    for (int s = PS_L / 2; s > 0; s >>= 1) {
        float v = sm_mass[pos + s - 1];
        bool adv = isLo ? (v < target) : (v <= target);
        pos += adv ? s : 0;
    }
    {   // final correction: rank may be pos or pos+1 (pos==4096 reachable only here)
        float v = sm_mass[pos];
        bool adv = isLo ? (v < target) : (v <= target);
        pos += adv ? 1 : 0;
    }
    const int base = lane & ~7;           // first lane of this peak group
    const int lo = __shfl_sync(0xFFFFFFFF, pos, base + 0);
    const int hi = __shfl_sync(0xFFFFFFFF, pos, base + 4);

    // w = exp2(c2*d*d), keep iff c2*d*d >= -10*log2(e).
    const float c2  = -0.5f * inv_s2 * LOG2E;
    const float th2 = -10.0f * LOG2E;

    float acc0 = 0.0f, acc1 = 0.0f;
    int i = lo + q;
    #pragma unroll 1
    for (; i + LANES < hi; i += 2 * LANES) {
        float x0 = sm_mass[i];
        float x1 = sm_mass[i + LANES];
        float y0 = iv[i];
        float y1 = iv[i + LANES];
        float d0 = x0 - m;
        float d1 = x1 - m;
        float a0 = c2 * d0 * d0;
        float a1 = c2 * d1 * d1;
        float e0 = ex2_approx(a0);
        float e1 = ex2_approx(a1);
        float w0 = (a0 >= th2) ? e0 : 0.0f;
        float w1 = (a1 >= th2) ? e1 : 0.0f;
        acc0 = fmaf(w0, y0, acc0);
        acc1 = fmaf(w1, y1, acc1);
    }
    if (i < hi) {
        float d = sm_mass[i] - m;
        float a = c2 * d * d;
        float e = ex2_approx(a);
        float w = (a >= th2) ? e : 0.0f;
        acc0 = fmaf(w, iv[i], acc0);
    }

    // Reduce the 8 lanes of this peak.
    float acc = acc0 + acc1;
    acc += __shfl_xor_sync(0xFFFFFFFF, acc, 1);
    acc += __shfl_xor_sync(0xFFFFFFFF, acc, 2);
    acc += __shfl_xor_sync(0xFFFFFFFF, acc, 4);

    if (q == 0) out[(size_t)b * PS_N + p] = acc;
}

extern "C" void kernel_launch(void* const* d_in, const int* in_sizes, int n_in,
                              void* d_out, int out_size) {
    const float* mu     = (const float*)d_in[0];
    const float* lv     = (const float*)d_in[1];
    const float* masses = (const float*)d_in[2];
    const float* intens = (const float*)d_in[3];
    float* out = (float*)d_out;

    dim3 grid(GROUPS, PS_B);
    peaksense_kernel<<<grid, THREADS>>>(mu, lv, masses, intens, out);
}

// round 9
// speedup vs baseline: 1.0657x; 1.0030x over previous
#include <cuda_runtime.h>

// PeakSense: out[b,p] = sum_i exp(-0.5*(mass[b,i]-mu[p])^2 * exp(-lv[p])) * iv[b,i],
// terms with arg < -10 dropped. Masses sorted per batch -> per-peak window.
//
// R9: warp-cooperative adjacent peaks. Peak windows (15.7 mass units) overlap
// ~75% across adjacent peaks (spacing 3.53), so ONE WARP processes 4 adjacent
// peaks over their UNION window: each lane loads one (mass, iv) — fully
// coalesced, 1 wavefront — and evaluates 4 weights. 2 searches/warp (half-warp
// split on union bounds) instead of 8. Exact per-peak in-loop predicate keeps
// correctness; the union is just a superset.

#define PS_B 128
#define PS_L 4096
#define PS_N 256
#define GROUPS 8                          // blocks per batch
#define PEAKS_PER_BLOCK (PS_N / GROUPS)   // 32
#define WARPS 8                           // 4 peaks per warp
#define THREADS (WARPS * 32)              // 256
#define LOG2E 1.4426950408889634f

__device__ __forceinline__ float ex2_approx(float x) {
    float r;
    asm("ex2.approx.f32 %0, %1;" : "=f"(r) : "f"(x));
    return r;
}
__device__ __forceinline__ float sqrt_approx(float x) {
    float r;
    asm("sqrt.approx.f32 %0, %1;" : "=f"(r) : "f"(x));
    return r;
}

__global__ __launch_bounds__(THREADS)
void peaksense_kernel(const float* __restrict__ mu,
                      const float* __restrict__ lv,
                      const float* __restrict__ masses,
                      const float* __restrict__ intens,
                      float* __restrict__ out) {
    __shared__ float sm_mass[PS_L];       // 16 KB

    const int b    = blockIdx.y;
    const int tid  = threadIdx.x;
    const int wid  = tid >> 5;
    const int lane = tid & 31;
    const int pbase = blockIdx.x * PEAKS_PER_BLOCK + wid * 4;

    // Stage this batch's masses into shared (float4, 4 per thread, MLP=4).
    {
        const float4* m4 = reinterpret_cast<const float4*>(masses + (size_t)b * PS_L);
        float4* s4 = reinterpret_cast<float4*>(sm_mass);
        #pragma unroll
        for (int i = tid; i < PS_L / 4; i += THREADS) s4[i] = m4[i];
    }

    const float* __restrict__ iv = intens + (size_t)b * PS_L;

    // Per-peak params for the warp's 4 adjacent peaks (broadcast LDG: all
    // lanes read the same 4 addresses -> 1 wavefront each).
    float mus[4], c2s[4];
    float uLob =  1e30f, uHib = -1e30f;
    #pragma unroll
    for (int j = 0; j < 4; ++j) {
        float mj = mu[pbase + j];
        float lj = lv[pbase + j];
        float inv_s2 = __expf(-lj);            // 1/sigma^2 (MUFU)
        // R^2 = 20/inv_s2 = 20*exp(lv); approx sqrt + inflation is fine —
        // the exact in-loop predicate is the real filter.
        float R = sqrt_approx(20.0f * __expf(lj)) * 1.001f + 1e-4f;
        mus[j] = mj;
        c2s[j] = -0.5f * inv_s2 * LOG2E;       // a = c2*d*d (log2 domain)
        uLob = fminf(uLob, mj - R);
        uHib = fmaxf(uHib, mj + R);
    }
    const float th2 = -10.0f * LOG2E;

    __syncthreads();

    // Half-warp split branchless rank search (12 steps + final correction,
    // verified in R7/R8). Lanes 0-15: first >= uLob. Lanes 16-31: first > uHib.
    const bool  isLo   = (lane < 16);
    const float target = isLo ? uLob : uHib;
    int pos = 0;
    #pragma unroll
    for (int s = PS_L / 2; s > 0; s >>= 1) {
        float v = sm_mass[pos + s - 1];
        bool adv = isLo ? (v < target) : (v <= target);
        pos += adv ? s : 0;
    }
    {
        float v = sm_mass[pos];
        bool adv = isLo ? (v < target) : (v <= target);
        pos += adv ? 1 : 0;
    }
    const int lo = __shfl_sync(0xFFFFFFFF, pos, 0);
    const int hi = __shfl_sync(0xFFFFFFFF, pos, 16);

    // Union-window loop: lane reads ONE consecutive (mass, iv) per iteration
    // (coalesced LDS + LDG), evaluates all 4 peaks' weights against it.
    float acc0 = 0.0f, acc1 = 0.0f, acc2 = 0.0f, acc3 = 0.0f;
    #pragma unroll 1
    for (int i = lo + lane; i < hi; i += 32) {
        float x = sm_mass[i];
        float y = iv[i];

        float d0 = x - mus[0];
        float d1 = x - mus[1];
        float d2 = x - mus[2];
        float d3 = x - mus[3];
        float a0 = c2s[0] * d0 * d0;
        float a1 = c2s[1] * d1 * d1;
        float a2 = c2s[2] * d2 * d2;
        float a3 = c2s[3] * d3 * d3;
        float w0 = (a0 >= th2) ? ex2_approx(a0) : 0.0f;
        float w1 = (a1 >= th2) ? ex2_approx(a1) : 0.0f;
        float w2 = (a2 >= th2) ? ex2_approx(a2) : 0.0f;
        float w3 = (a3 >= th2) ? ex2_approx(a3) : 0.0f;
        acc0 = fmaf(w0, y, acc0);
        acc1 = fmaf(w1, y, acc1);
        acc2 = fmaf(w2, y, acc2);
        acc3 = fmaf(w3, y, acc3);
    }

    // Reduce each accumulator across the warp.
    #pragma unroll
    for (int s = 16; s > 0; s >>= 1) {
        acc0 += __shfl_xor_sync(0xFFFFFFFF, acc0, s);
        acc1 += __shfl_xor_sync(0xFFFFFFFF, acc1, s);
        acc2 += __shfl_xor_sync(0xFFFFFFFF, acc2, s);
        acc3 += __shfl_xor_sync(0xFFFFFFFF, acc3, s);
    }

    if (lane == 0) {
        float* o = out + (size_t)b * PS_N + pbase;
        o[0] = acc0;
        o[1] = acc1;
        o[2] = acc2;
        o[3] = acc3;
    }
}

extern "C" void kernel_launch(void* const* d_in, const int* in_sizes, int n_in,
                              void* d_out, int out_size) {
    const float* mu     = (const float*)d_in[0];
    const float* lv     = (const float*)d_in[1];
    const float* masses = (const float*)d_in[2];
    const float* intens = (const float*)d_in[3];
    float* out = (float*)d_out;

    dim3 grid(GROUPS, PS_B);
    peaksense_kernel<<<grid, THREADS>>>(mu, lv, masses, intens, out);
}